// round 5
// baseline (speedup 1.0000x reference)
#include <cuda_runtime.h>
#include <cstdint>

#define NN 13
#define HD 128
#define NLAYER 8
#define NJ 17
#define DMAX 33
#define OBSD 348
#define SPC 8                  // samples per CTA
#define MREAL 104              // SPC*NN rows
#define XST 260                // xs row stride (floats): 256 dup + pad
#define ZST 130                // zbuf / h row stride
#define NTHREADS 512
#define KC 32                  // k rows per weight chunk
#define NCHUNK 4               // 128 / KC

// scratch layout (floats, after xs):
#define BUF0_OFF 0             // wb buffer 0: 32x256 = 8192 floats
#define BUF1_OFF 8192          // wb buffer 1 (aliases zbuf head)
#define ZB_OFF   8192          // zbuf/h: 104x130 = 13520 floats -> ends 21712
#define OBS_OFF  21712         // obs tile: 8x348 = 2784 -> ends 24496
#define SCR_FLOATS 24496
#define XS_FLOATS (MREAL*XST)  // 27040

__constant__ int c_feat[NN][DMAX] = {
  {0,1,2,3,4,22,23,24,25,26,27,45,46,47,48,49,50,51,52,53,54,175,176,177,178,179,180,270,271,272,273,274,275},
  {5,6,28,29,55,56,57,58,59,60,61,62,63,64,181,182,183,184,185,186,276,277,278,279,280,281,0,0,0,0,0,0,0},
  {7,30,65,66,67,68,69,70,71,72,73,74,187,188,189,190,191,192,253,254,255,282,283,284,285,286,287,0,0,0,0,0,0},
  {8,9,10,11,31,32,33,34,75,76,77,78,79,80,81,82,83,84,193,194,195,196,197,198,256,257,258,288,289,290,291,292,293},
  {11,34,85,86,87,88,89,90,91,92,93,94,199,200,201,202,203,204,259,294,295,296,297,298,299,0,0,0,0,0,0,0,0},
  {95,96,97,98,99,100,101,102,103,104,205,206,207,208,209,210,300,301,302,303,304,305,0,0,0,0,0,0,0,0,0,0,0},
  {12,13,14,15,35,36,37,38,105,106,107,108,109,110,111,112,113,114,211,212,213,214,215,216,260,261,262,306,307,308,309,310,311},
  {15,38,115,116,117,118,119,120,121,122,123,124,217,218,219,220,221,222,263,312,313,314,315,316,317,0,0,0,0,0,0,0,0},
  {125,126,127,128,129,130,131,132,133,134,223,224,225,226,227,228,318,319,320,321,322,323,0,0,0,0,0,0,0,0,0,0,0},
  {16,17,18,39,40,41,135,136,137,138,139,140,141,142,143,144,229,230,231,232,233,234,264,265,324,325,326,327,328,329,0,0,0},
  {18,41,145,146,147,148,149,150,151,152,153,154,235,236,237,238,239,240,266,330,331,332,333,334,335,0,0,0,0,0,0,0,0},
  {19,20,21,42,43,44,155,156,157,158,159,160,161,162,163,164,241,242,243,244,245,246,267,268,336,337,338,339,340,341,0,0,0},
  {21,44,165,166,167,168,169,170,171,172,173,174,247,248,249,250,251,252,269,342,343,344,345,346,347,0,0,0,0,0,0,0,0}
};
__constant__ int c_dcnt[NN] = {33,26,27,33,25,22,33,25,22,30,25,30,25};

__constant__ int c_nbr[NN][3] = {
  {1,9,11},{0,2,0},{1,3,6},{2,4,0},{3,5,0},{4,0,0},{2,7,0},
  {6,8,0},{7,0,0},{0,10,0},{9,0,0},{0,12,0},{11,0,0}
};
__constant__ int c_deg[NN] = {3,2,3,2,2,1,2,2,1,2,1,2,1};

__constant__ int c_jm0[NJ] = {1,1,1,2,2,2,3,2,2,2,6,0,0,9,0,0,11};
__constant__ int c_jm1[NJ] = {2,2,2,3,3,3,4,6,6,6,7,9,9,10,11,11,12};

__device__ __forceinline__ float eluf(float x) {
    return x > 0.0f ? x : expm1f(x);
}
__device__ __forceinline__ unsigned long long pk2(float lo, float hi) {
    unsigned long long r;
    asm("mov.b64 %0, {%1, %2};" : "=l"(r) : "f"(lo), "f"(hi));
    return r;
}
__device__ __forceinline__ void upk2(unsigned long long v, float& lo, float& hi) {
    asm("mov.b64 {%0, %1}, %2;" : "=f"(lo), "=f"(hi) : "l"(v));
}
// Blackwell packed dual-FP32 FMA: 2 exact fp32 FMAs per issue slot
__device__ __forceinline__ void fma2(unsigned long long& d, unsigned long long a, unsigned long long b) {
    asm("fma.rn.f32x2 %0, %1, %2, %0;" : "+l"(d) : "l"(a), "l"(b));
}
__device__ __forceinline__ void cpa16(uint32_t s, const float* g) {
    asm volatile("cp.async.cg.shared.global [%0], [%1], 16;\n" :: "r"(s), "l"(g));
}
__device__ __forceinline__ void cpa_commit() {
    asm volatile("cp.async.commit_group;\n" ::: "memory");
}
__device__ __forceinline__ void cpa_wait0() {
    asm volatile("cp.async.wait_group 0;\n" ::: "memory");
}

// stage KC=32 rows of W_top and W_bot (same k range) into buf as [kk][0:128 top |128:256 bot]
__device__ __forceinline__ void stage_chunk(const float* Wl, int cc, float* buf, int tid) {
    uint32_t b = (uint32_t)__cvta_generic_to_shared(buf);
    #pragma unroll
    for (int j = 0; j < 2; ++j) {
        int f2 = tid + j * NTHREADS;          // 0..1023 : top half, 32 rows x 32 float4
        int kk = f2 >> 5, c4 = f2 & 31;
        cpa16(b + (uint32_t)(kk * 256 + c4 * 4) * 4,
              Wl + (cc * KC + kk) * HD + c4 * 4);
    }
    #pragma unroll
    for (int j = 0; j < 2; ++j) {
        int f2 = tid + j * NTHREADS;          // bot half: W rows 128+
        int kk = f2 >> 5, c4 = f2 & 31;
        cpa16(b + (uint32_t)(kk * 256 + HD + c4 * 4) * 4,
              Wl + (HD + cc * KC + kk) * HD + c4 * 4);
    }
}

__global__ __launch_bounds__(NTHREADS, 1)
void gnn_kernel(const float* __restrict__ obs,
                const float* __restrict__ W1, const float* __restrict__ b1,
                const float* __restrict__ W2, const float* __restrict__ b2,
                const float* __restrict__ Wmsg, const float* __restrict__ bmsg,
                const float* __restrict__ Wout, const float* __restrict__ bout,
                float* __restrict__ out)
{
    extern __shared__ float sm[];
    float* xs  = sm;                  // [104][260] duplicated x: xs[m][2k]=xs[m][2k+1]=x[m][k]
    float* scr = sm + XS_FLOATS;
    float* zb  = scr + ZB_OFF;        // z buffer / encoder hidden, [104][130]
    float* obsb= scr + OBS_OFF;

    const int tid = threadIdx.x;
    const int base_s = blockIdx.x * SPC;
    const int tx = tid & 31;          // ull col pairs: j0 -> cols (2tx,2tx+1), j1 -> (2tx+64,2tx+65)
    const int ty = tid >> 5;          // warp index / row group

    // ======== load obs tile ========
    {
        const float4* g = (const float4*)(obs + (size_t)base_s * OBSD);
        float4* o4 = (float4*)obsb;
        for (int i = tid; i < SPC * OBSD / 4; i += NTHREADS) o4[i] = g[i];
    }
    // prefetch layer-0 chunk-0 weights (buf0 disjoint from h/obs regions)
    stage_chunk(Wmsg, 0, scr + BUF0_OFF, tid);
    cpa_commit();
    __syncthreads();

    // ======== encoder phase 1: h = elu(gather(obs) @ W1[n] + b1[n]) -> zb ========
    if (ty < NN) {
        const int n = ty;
        unsigned long long acc[SPC][2];
        {
            const unsigned long long* bp = (const unsigned long long*)(b1 + n * HD);
            unsigned long long b0 = bp[tx], b1v = bp[tx + 32];
            #pragma unroll
            for (int s = 0; s < SPC; ++s) { acc[s][0] = b0; acc[s][1] = b1v; }
        }
        const int dc = c_dcnt[n];
        #pragma unroll 1
        for (int d = 0; d < dc; ++d) {
            const int fi = c_feat[n][d];
            const unsigned long long* wr =
                (const unsigned long long*)(W1 + (n * DMAX + d) * HD);
            unsigned long long w0 = wr[tx], w1 = wr[tx + 32];
            #pragma unroll
            for (int s = 0; s < SPC; ++s) {
                float xe = obsb[s * OBSD + fi];
                unsigned long long p = pk2(xe, xe);
                fma2(acc[s][0], p, w0); fma2(acc[s][1], p, w1);
            }
        }
        #pragma unroll
        for (int s = 0; s < SPC; ++s) {
            float* dst = zb + (s * NN + n) * ZST;
            float lo, hi;
            upk2(acc[s][0], lo, hi);
            *(float2*)(dst + 2 * tx) = make_float2(eluf(lo), eluf(hi));
            upk2(acc[s][1], lo, hi);
            *(float2*)(dst + 2 * tx + 64) = make_float2(eluf(lo), eluf(hi));
        }
    }
    __syncthreads();

    // ======== encoder phase 2: x0 = h @ W2[n] + b2[n] -> xs (duplicated) ========
    if (ty < NN) {
        const int n = ty;
        unsigned long long acc[SPC][2];
        {
            const unsigned long long* bp = (const unsigned long long*)(b2 + n * HD);
            unsigned long long b0 = bp[tx], b1v = bp[tx + 32];
            #pragma unroll
            for (int s = 0; s < SPC; ++s) { acc[s][0] = b0; acc[s][1] = b1v; }
        }
        #pragma unroll 2
        for (int k = 0; k < HD; ++k) {
            const unsigned long long* wr =
                (const unsigned long long*)(W2 + (n * HD + k) * HD);
            unsigned long long w0 = wr[tx], w1 = wr[tx + 32];
            #pragma unroll
            for (int s = 0; s < SPC; ++s) {
                float xe = zb[(s * NN + n) * ZST + k];
                unsigned long long p = pk2(xe, xe);
                fma2(acc[s][0], p, w0); fma2(acc[s][1], p, w1);
            }
        }
        #pragma unroll
        for (int s = 0; s < SPC; ++s) {
            float* dst = xs + (s * NN + n) * XST;
            float lo, hi;
            upk2(acc[s][0], lo, hi);
            *(float4*)(dst + 4 * tx) = make_float4(lo, lo, hi, hi);
            upk2(acc[s][1], lo, hi);
            *(float4*)(dst + 4 * tx + 128) = make_float4(lo, lo, hi, hi);
        }
    }
    // NOTE: no sync here; the kc=0 sync inside the layer loop orders phase-2
    // writes (xs, read after that sync) and protects zb before chunk-1 staging.

    // SMSP-balanced row tiling: ty<8 -> 7 rows, ty>=8 -> 6 rows (total 104)
    const int R = (ty < 8) ? 7 : 6;
    const int row0 = (ty < 8) ? ty * 7 : 56 + (ty - 8) * 6;
    int xoff[7];
    #pragma unroll
    for (int r = 0; r < 7; ++r) xoff[r] = (row0 + ((r < R) ? r : R - 1)) * XST;

    // ======== 8 message-passing layers ========
    // out[m] = elu( x[m]@W_top + sum_nb x[nb]@W_bot + bias )
    for (int l = 0; l < NLAYER; ++l) {
        const float* Wl = Wmsg + (size_t)l * 256 * HD;

        unsigned long long accy[7][2], accz[7][2];
        {
            const unsigned long long* bp = (const unsigned long long*)(bmsg + l * HD);
            unsigned long long b0 = bp[tx], b1v = bp[tx + 32];
            #pragma unroll
            for (int r = 0; r < 7; ++r) {
                accy[r][0] = b0; accy[r][1] = b1v;
                accz[r][0] = 0ULL; accz[r][1] = 0ULL;
            }
        }

        for (int kc = 0; kc < NCHUNK; ++kc) {
            cpa_wait0();
            __syncthreads();
            if (kc + 1 < NCHUNK) {
                stage_chunk(Wl, kc + 1, scr + ((kc + 1) & 1) * BUF1_OFF, tid);
                cpa_commit();
            }
            const float* wt = scr + (kc & 1) * BUF1_OFF;
            const float* xk = xs + kc * (2 * KC);
            #pragma unroll 1
            for (int k2 = 0; k2 < KC; k2 += 2) {
                ulonglong2 a[7];
                #pragma unroll
                for (int r = 0; r < 7; ++r)
                    a[r] = *(const ulonglong2*)(xk + xoff[r] + 2 * k2);
                #pragma unroll
                for (int kk = 0; kk < 2; ++kk) {
                    const unsigned long long* wr =
                        (const unsigned long long*)(wt + (k2 + kk) * 256);
                    unsigned long long wy0 = wr[tx],      wy1 = wr[tx + 32];
                    unsigned long long wz0 = wr[64 + tx], wz1 = wr[64 + tx + 32];
                    #pragma unroll
                    for (int r = 0; r < 7; ++r) {
                        unsigned long long p = kk ? a[r].y : a[r].x;
                        fma2(accy[r][0], p, wy0);
                        fma2(accy[r][1], p, wy1);
                        fma2(accz[r][0], p, wz0);
                        fma2(accz[r][1], p, wz1);
                    }
                }
            }
        }
        __syncthreads();     // all warps done reading buf1 (zb aliases it)
        // store z
        #pragma unroll
        for (int r = 0; r < 7; ++r) {
            if (r < R) {
                float* dst = zb + (row0 + r) * ZST;
                float lo, hi;
                upk2(accz[r][0], lo, hi);
                *(float2*)(dst + 2 * tx) = make_float2(lo, hi);
                upk2(accz[r][1], lo, hi);
                *(float2*)(dst + 2 * tx + 64) = make_float2(lo, hi);
            }
        }
        __syncthreads();     // z visible to all
        // prefetch next layer's chunk 0 into buf0 (disjoint from zb) — overlaps combine
        if (l + 1 < NLAYER) {
            stage_chunk(Wmsg + (size_t)(l + 1) * 256 * HD, 0, scr + BUF0_OFF, tid);
            cpa_commit();
        }
        // combine: out = elu(y + sum_nb z[nb]), write duplicated into xs
        #pragma unroll
        for (int r = 0; r < 7; ++r) {
            if (r < R) {
                const int m = row0 + r;
                const int n = m % NN;
                const int s13 = m - n;
                const int dg = c_deg[n];
                float2 zs0, zs1;
                {
                    const float* zr = zb + (s13 + c_nbr[n][0]) * ZST + 2 * tx;
                    zs0 = *(const float2*)(zr);
                    zs1 = *(const float2*)(zr + 64);
                }
                #pragma unroll
                for (int e = 1; e < 3; ++e)
                    if (e < dg) {
                        const float* zr = zb + (s13 + c_nbr[n][e]) * ZST + 2 * tx;
                        float2 v0 = *(const float2*)(zr);
                        float2 v1 = *(const float2*)(zr + 64);
                        zs0.x += v0.x; zs0.y += v0.y;
                        zs1.x += v1.x; zs1.y += v1.y;
                    }
                float* dst = xs + m * XST;
                float lo, hi;
                upk2(accy[r][0], lo, hi);
                lo = eluf(lo + zs0.x); hi = eluf(hi + zs0.y);
                *(float4*)(dst + 4 * tx) = make_float4(lo, lo, hi, hi);
                upk2(accy[r][1], lo, hi);
                lo = eluf(lo + zs1.x); hi = eluf(hi + zs1.y);
                *(float4*)(dst + 4 * tx + 128) = make_float4(lo, lo, hi, hi);
            }
        }
        // next layer's kc=0 __syncthreads orders these xs writes
    }
    __syncthreads();

    // ======== joint readout (xs is duplicated: x[m][c] at xs[m][2c]) ========
    const int lane = tid & 31;
    const int wrp = tid >> 5;
    for (int t = wrp; t < SPC * NJ; t += NTHREADS / 32) {
        int s = t / NJ, j = t - s * NJ;
        const float* r0 = xs + (s * NN + c_jm0[j]) * XST + 8 * lane;
        const float* r1 = xs + (s * NN + c_jm1[j]) * XST + 8 * lane;
        const float* wj = Wout + j * 2 * HD + 4 * lane;
        float4 xa = *(const float4*)(r0);
        float4 xb = *(const float4*)(r0 + 4);
        float4 ya = *(const float4*)(r1);
        float4 yb = *(const float4*)(r1 + 4);
        float4 w0 = *(const float4*)(wj);
        float4 w1 = *(const float4*)(wj + HD);
        float sum = xa.x * w0.x + xa.z * w0.y + xb.x * w0.z + xb.z * w0.w
                  + ya.x * w1.x + ya.z * w1.y + yb.x * w1.z + yb.z * w1.w;
        #pragma unroll
        for (int o = 16; o; o >>= 1)
            sum += __shfl_xor_sync(0xffffffffu, sum, o);
        if (lane == 0)
            out[(size_t)(base_s + s) * NJ + j] = sum + bout[j];
    }
}

extern "C" void kernel_launch(void* const* d_in, const int* in_sizes, int n_in,
                              void* d_out, int out_size) {
    const float* obs  = (const float*)d_in[0];
    const float* W1   = (const float*)d_in[1];
    const float* b1   = (const float*)d_in[2];
    const float* W2   = (const float*)d_in[3];
    const float* b2   = (const float*)d_in[4];
    const float* Wmsg = (const float*)d_in[5];
    const float* bmsg = (const float*)d_in[6];
    const float* Wout = (const float*)d_in[7];
    const float* bout = (const float*)d_in[8];
    float* out = (float*)d_out;

    int B = in_sizes[0] / OBSD;
    int nblk = B / SPC;
    size_t smem = (size_t)(XS_FLOATS + SCR_FLOATS) * sizeof(float); // 206,144 B

    cudaFuncSetAttribute(gnn_kernel, cudaFuncAttributeMaxDynamicSharedMemorySize, (int)smem);
    gnn_kernel<<<nblk, NTHREADS, smem>>>(obs, W1, b1, W2, b2, Wmsg, bmsg, Wout, bout, out);
}